// round 4
// baseline (speedup 1.0000x reference)
#include <cuda_runtime.h>
#include <cuda_bf16.h>
#include <math.h>
#include <stdint.h>

// ---------------- dims ----------------
#define B2   2
#define L_   2048
#define DM_  1024
#define DI_  2048
#define NS_  16
#define RR_  64
#define ML_  (B2 * L_)          // 4096
#define XZW  (2 * DI_)          // 4096
#define XDP  128                // padded xdbl width (96 -> 128)
#define KSPLIT 4

// ---------------- scratch (device globals) ----------------
__device__ float g_xz  [(size_t)ML_ * XZW];
__device__ float g_u   [(size_t)ML_ * DI_];
__device__ float g_xdbl[(size_t)ML_ * XDP];
__device__ float g_xpp [KSPLIT][(size_t)ML_ * XDP];   // split-K partials
__device__ float g_dt  [(size_t)ML_ * DI_];
__device__ float g_y   [(size_t)ML_ * DI_];
__device__ __nv_bfloat16 g_hb   [(size_t)ML_ * DM_];
__device__ __nv_bfloat16 g_ub   [(size_t)ML_ * DI_];
__device__ __nv_bfloat16 g_ygb  [(size_t)ML_ * DI_];
__device__ __nv_bfloat16 g_dtrb [(size_t)ML_ * RR_];
__device__ __nv_bfloat16 g_w_in [(size_t)XZW * DM_];
__device__ __nv_bfloat16 g_w_xp [(size_t)XDP * DI_];
__device__ __nv_bfloat16 g_w_dt [(size_t)DI_ * RR_];
__device__ __nv_bfloat16 g_w_out[(size_t)DM_ * DI_];

// ---------------- asm helpers ----------------
__device__ __forceinline__ uint32_t smem_u32(const void* p) {
    uint32_t a;
    asm("{ .reg .u64 t; cvta.to.shared.u64 t, %1; cvt.u32.u64 %0, t; }" : "=r"(a) : "l"(p));
    return a;
}
#define LDSM4(R0, R1, R2, R3, ADDR) \
    asm volatile("ldmatrix.sync.aligned.m8n8.x4.shared.b16 {%0,%1,%2,%3}, [%4];" \
        : "=r"(R0), "=r"(R1), "=r"(R2), "=r"(R3) : "r"(ADDR))
#define MMA16816(D, A0, A1, A2, A3, B0, B1) \
    asm volatile("mma.sync.aligned.m16n8k16.row.col.f32.bf16.bf16.f32 " \
        "{%0,%1,%2,%3}, {%4,%5,%6,%7}, {%8,%9}, {%0,%1,%2,%3};" \
        : "+f"((D)[0]), "+f"((D)[1]), "+f"((D)[2]), "+f"((D)[3]) \
        : "r"(A0), "r"(A1), "r"(A2), "r"(A3), "r"(B0), "r"(B1))
#define CP16(S, G) \
    asm volatile("cp.async.cg.shared.global [%0], [%1], 16;" :: "r"(S), "l"(G))
#define CPCOMMIT() asm volatile("cp.async.commit_group;")

#define NSTG 4
#define STAGE_BYTES 20480
#define ROW_B 80
#define SMEM_TOTAL (NSTG * STAGE_BYTES)   // 81920

// ---------------- bf16 HMMA GEMM: C[M,N] = A[M,Klen] @ Bt[N,Klen]^T ----------------
// lda = row stride of A/Bt (elements); Klen = reduction length (multiple of 32).
// 128x128 tile, BK=32, 4-stage cp.async pipeline, 1 bar per iter.
// mode 0: C = acc ; 1: C = softplus(acc + e1[col]) ; 2: C = acc + e1[row*ldc + col]
__global__ void __launch_bounds__(256) hmma_gemm(
    const __nv_bfloat16* __restrict__ A, const __nv_bfloat16* __restrict__ Bt,
    float* __restrict__ C, int lda, int Klen, int ldc, int mode,
    const float* __restrict__ e1)
{
    extern __shared__ __align__(128) char smem[];
    uint32_t sb = smem_u32(smem);
    int tid = threadIdx.x, wid = tid >> 5, lane = tid & 31;
    int row0 = blockIdx.y * 128, col0 = blockIdx.x * 128;
    int m0 = (wid & 3) * 32, n0 = (wid >> 2) * 64;

    int rA0 = tid >> 2, q0 = tid & 3;
    int rA1 = (tid + 256) >> 2;
    const char* gA0 = (const char*)(A  + (size_t)(row0 + rA0) * lda + q0 * 8);
    const char* gA1 = (const char*)(A  + (size_t)(row0 + rA1) * lda + q0 * 8);
    const char* gB0 = (const char*)(Bt + (size_t)(col0 + rA0) * lda + q0 * 8);
    const char* gB1 = (const char*)(Bt + (size_t)(col0 + rA1) * lda + q0 * 8);
    uint32_t sA0 = sb + rA0 * ROW_B + q0 * 16;
    uint32_t sA1 = sb + rA1 * ROW_B + q0 * 16;
    uint32_t sB0 = sA0 + 10240;
    uint32_t sB1 = sA1 + 10240;

    uint32_t aBase = sb + (m0 + (lane & 15)) * ROW_B + ((lane >> 4) << 4);
    uint32_t bBase = sb + 10240 + (n0 + (lane & 15)) * ROW_B + ((lane >> 4) << 4);

    float acc[2][8][4];
    #pragma unroll
    for (int i = 0; i < 2; i++)
        #pragma unroll
        for (int j = 0; j < 8; j++)
            #pragma unroll
            for (int v = 0; v < 4; v++) acc[i][j][v] = 0.f;

    const int NK = Klen >> 5;
    // prologue: issue up to 3 stages, always commit 3 groups
    #pragma unroll
    for (int s = 0; s < NSTG - 1; s++) {
        if (s < NK) {
            uint32_t so = s * STAGE_BYTES;
            size_t go = (size_t)s * 64;
            CP16(sA0 + so, gA0 + go); CP16(sA1 + so, gA1 + go);
            CP16(sB0 + so, gB0 + go); CP16(sB1 + so, gB1 + go);
        }
        CPCOMMIT();
    }

    for (int kt = 0; kt < NK; kt++) {
        asm volatile("cp.async.wait_group %0;" :: "n"(NSTG - 2));
        __syncthreads();
        // issue stage kt+3
        if (kt + NSTG - 1 < NK) {
            uint32_t so = ((kt + NSTG - 1) & (NSTG - 1)) * STAGE_BYTES;
            size_t go = (size_t)(kt + NSTG - 1) * 64;
            CP16(sA0 + so, gA0 + go); CP16(sA1 + so, gA1 + go);
            CP16(sB0 + so, gB0 + go); CP16(sB1 + so, gB1 + go);
        }
        CPCOMMIT();

        uint32_t so = (kt & (NSTG - 1)) * STAGE_BYTES;
        #pragma unroll
        for (int s = 0; s < 2; s++) {
            uint32_t a[2][4], b[4][4];
            #pragma unroll
            for (int mt = 0; mt < 2; mt++)
                LDSM4(a[mt][0], a[mt][1], a[mt][2], a[mt][3],
                      aBase + so + s * 32 + mt * (16 * ROW_B));
            #pragma unroll
            for (int g = 0; g < 4; g++)
                LDSM4(b[g][0], b[g][1], b[g][2], b[g][3],
                      bBase + so + s * 32 + g * (16 * ROW_B));
            #pragma unroll
            for (int mt = 0; mt < 2; mt++)
                #pragma unroll
                for (int j = 0; j < 8; j++) {
                    int g = j >> 1, o = j & 1;
                    MMA16816(acc[mt][j], a[mt][0], a[mt][1], a[mt][2], a[mt][3],
                             b[g][o], b[g][o + 2]);
                }
        }
    }

    // epilogue
    #pragma unroll
    for (int mt = 0; mt < 2; mt++) {
        #pragma unroll
        for (int j = 0; j < 8; j++) {
            int r_ = row0 + m0 + mt * 16 + (lane >> 2);
            int c_ = col0 + n0 + j * 8 + (lane & 3) * 2;
            #pragma unroll
            for (int h = 0; h < 2; h++) {
                float v0 = acc[mt][j][h * 2], v1 = acc[mt][j][h * 2 + 1];
                int rr = r_ + h * 8;
                if (mode == 1) {
                    v0 += e1[c_];
                    v1 += e1[c_ + 1];
                    v0 = fmaxf(v0, 0.f) + __logf(1.f + __expf(-fabsf(v0)));
                    v1 = fmaxf(v1, 0.f) + __logf(1.f + __expf(-fabsf(v1)));
                } else if (mode == 2) {
                    const float2 xv = *(const float2*)(e1 + (size_t)rr * ldc + c_);
                    v0 += xv.x; v1 += xv.y;
                }
                *(float2*)(C + (size_t)rr * ldc + c_) = make_float2(v0, v1);
            }
        }
    }
}

// ---------------- transpose fp32 [K,Nin] -> bf16 [Nout,K] (zero-pad) ----------------
__global__ void transpose_bf16(const float* __restrict__ in, __nv_bfloat16* __restrict__ out,
                               int K, int Nin, int Nout) {
    __shared__ float tile[32][33];
    int kb = blockIdx.x * 32, nb = blockIdx.y * 32;
    int tx = threadIdx.x, ty = threadIdx.y;
    #pragma unroll
    for (int i = 0; i < 32; i += 8) {
        int k = kb + ty + i, n = nb + tx;
        tile[ty + i][tx] = (n < Nin) ? in[(size_t)k * Nin + n] : 0.f;
    }
    __syncthreads();
    #pragma unroll
    for (int i = 0; i < 32; i += 8) {
        int n = nb + ty + i, k = kb + tx;
        out[(size_t)n * K + k] = __float2bfloat16(tile[tx][ty + i]);
    }
}

// ---------------- RMSNorm -> bf16 ----------------
__global__ void __launch_bounds__(256) rmsnorm_kernel(const float* __restrict__ x,
                                                      const float* __restrict__ w) {
    int row = blockIdx.x;
    int tid = threadIdx.x;
    float4 v = ((const float4*)(x + (size_t)row * DM_))[tid];
    float ss = v.x * v.x + v.y * v.y + v.z * v.z + v.w * v.w;
    #pragma unroll
    for (int o = 16; o > 0; o >>= 1) ss += __shfl_xor_sync(0xffffffffu, ss, o);
    __shared__ float sm[8];
    if ((tid & 31) == 0) sm[tid >> 5] = ss;
    __syncthreads();
    float tot = sm[0] + sm[1] + sm[2] + sm[3] + sm[4] + sm[5] + sm[6] + sm[7];
    float s = rsqrtf(tot * (1.0f / DM_) + 1e-5f);
    float4 wv = ((const float4*)w)[tid];
    __nv_bfloat162* op = (__nv_bfloat162*)(g_hb + (size_t)row * DM_);
    op[tid * 2]     = __floats2bfloat162_rn(v.x * s * wv.x, v.y * s * wv.y);
    op[tid * 2 + 1] = __floats2bfloat162_rn(v.z * s * wv.z, v.w * s * wv.w);
}

// ---------------- causal depthwise conv (K=4) + bias + SiLU ----------------
__global__ void __launch_bounds__(256) conv_silu_kernel(const float* __restrict__ conv_w,
                                                        const float* __restrict__ conv_b) {
    int idx = blockIdx.x * 256 + threadIdx.x;
    int d = idx & (DI_ - 1);
    int row = idx >> 11;
    int t = row & (L_ - 1);
    float w0 = conv_w[d * 4 + 0], w1 = conv_w[d * 4 + 1];
    float w2 = conv_w[d * 4 + 2], w3 = conv_w[d * 4 + 3];
    const float* base = g_xz + (size_t)row * XZW + d;
    float acc = conv_b[d] + base[0] * w3;
    if (t >= 1) acc = fmaf(base[-(ptrdiff_t)XZW], w2, acc);
    if (t >= 2) acc = fmaf(base[-2 * (ptrdiff_t)XZW], w1, acc);
    if (t >= 3) acc = fmaf(base[-3 * (ptrdiff_t)XZW], w0, acc);
    float u = acc / (1.f + __expf(-acc));
    g_u[idx] = u;
    g_ub[idx] = __float2bfloat16(u);
}

// ---------------- reduce split-K partials -> g_xdbl fp32 + g_dtrb bf16 ----------------
__global__ void __launch_bounds__(256) xp_reduce_kernel() {
    int idx = blockIdx.x * 256 + threadIdx.x;      // over ML_*XDP
    float s = g_xpp[0][idx] + g_xpp[1][idx] + g_xpp[2][idx] + g_xpp[3][idx];
    g_xdbl[idx] = s;
    int j = idx & (XDP - 1);
    if (j < RR_) g_dtrb[((size_t)(idx >> 7) << 6) + j] = __float2bfloat16(s);
}

// ---------------- selective scan ----------------
// 512 blocks x 128 threads; 8 channels per block (2 per warp, 16 lanes each).
__global__ void __launch_bounds__(128) scan_kernel(const float* __restrict__ A_log) {
    int tid = threadIdx.x;
    int lane = tid & 31;
    int n = lane & 15;
    int ch = tid >> 4;                       // 0..7
    int b = blockIdx.x >> 8;                 // 256 blocks per batch
    int d = ((blockIdx.x & 255) << 3) + ch;
    float A_n = -expf(A_log[d * NS_ + n]);
    float hst = 0.f;
    const float* dtp = g_dt + (size_t)b * L_ * DI_ + d;
    const float* up  = g_u  + (size_t)b * L_ * DI_ + d;
    const float* xb  = g_xdbl + (size_t)b * L_ * XDP;
    float* yp = g_y + (size_t)b * L_ * DI_ + d;
    #pragma unroll 4
    for (int t = 0; t < L_; t++) {
        float dt_v = __ldg(dtp + (size_t)t * DI_);
        float u_v  = __ldg(up  + (size_t)t * DI_);
        float Bn = __ldg(xb + t * XDP + RR_ + n);
        float Cn = __ldg(xb + t * XDP + RR_ + NS_ + n);
        float dA = __expf(dt_v * A_n);
        hst = fmaf(dA, hst, dt_v * u_v * Bn);
        float p = hst * Cn;
        p += __shfl_xor_sync(0xffffffffu, p, 8);
        p += __shfl_xor_sync(0xffffffffu, p, 4);
        p += __shfl_xor_sync(0xffffffffu, p, 2);
        p += __shfl_xor_sync(0xffffffffu, p, 1);
        if (n == 0) yp[(size_t)t * DI_] = p;
    }
}

// ---------------- gating: ygb = bf16((y + u*D) * silu(z)) ----------------
__global__ void __launch_bounds__(256) gate_kernel(const float* __restrict__ Dw) {
    int idx = blockIdx.x * 256 + threadIdx.x;
    int d = idx & (DI_ - 1);
    int row = idx >> 11;
    float z = g_xz[(size_t)row * XZW + DI_ + d];
    float sz = z / (1.f + __expf(-z));
    g_ygb[idx] = __float2bfloat16((g_y[idx] + g_u[idx] * Dw[d]) * sz);
}

// ---------------- launch ----------------
extern "C" void kernel_launch(void* const* d_in, const int* in_sizes, int n_in,
                              void* d_out, int out_size) {
    (void)in_sizes; (void)n_in; (void)out_size;
    const float* x          = (const float*)d_in[0];
    const float* norm_w     = (const float*)d_in[2];
    const float* in_proj_w  = (const float*)d_in[3];
    const float* conv_w     = (const float*)d_in[4];
    const float* conv_b     = (const float*)d_in[5];
    const float* x_proj_w   = (const float*)d_in[6];
    const float* dt_proj_w  = (const float*)d_in[7];
    const float* dt_proj_b  = (const float*)d_in[8];
    const float* A_log      = (const float*)d_in[9];
    const float* Dw         = (const float*)d_in[10];
    const float* out_proj_w = (const float*)d_in[11];
    float* out = (float*)d_out;

    float *p_xz, *p_dt, *p_xpp;
    __nv_bfloat16 *p_hb, *p_ub, *p_ygb, *p_dtrb, *p_w_in, *p_w_xp, *p_w_dt, *p_w_out;
    cudaGetSymbolAddress((void**)&p_xz, g_xz);
    cudaGetSymbolAddress((void**)&p_dt, g_dt);
    cudaGetSymbolAddress((void**)&p_xpp, g_xpp);
    cudaGetSymbolAddress((void**)&p_hb, g_hb);
    cudaGetSymbolAddress((void**)&p_ub, g_ub);
    cudaGetSymbolAddress((void**)&p_ygb, g_ygb);
    cudaGetSymbolAddress((void**)&p_dtrb, g_dtrb);
    cudaGetSymbolAddress((void**)&p_w_in, g_w_in);
    cudaGetSymbolAddress((void**)&p_w_xp, g_w_xp);
    cudaGetSymbolAddress((void**)&p_w_dt, g_w_dt);
    cudaGetSymbolAddress((void**)&p_w_out, g_w_out);

    cudaFuncSetAttribute(hmma_gemm, cudaFuncAttributeMaxDynamicSharedMemorySize, SMEM_TOTAL);

    dim3 tb(32, 8);
    // launch order arranged so index 3 (profiled) = in_proj GEMM
    transpose_bf16<<<dim3(DM_ / 32, XZW / 32), tb>>>(in_proj_w, p_w_in, DM_, XZW, XZW);   // 0
    rmsnorm_kernel<<<ML_, 256>>>(x, norm_w);                                              // 1
    transpose_bf16<<<dim3(DI_ / 32, DM_ / 32), tb>>>(out_proj_w, p_w_out, DI_, DM_, DM_); // 2
    // 3: xz = h @ in_proj_w   [4096 x 4096], K=1024
    hmma_gemm<<<dim3(XZW / 128, ML_ / 128), 256, SMEM_TOTAL>>>(
        p_hb, p_w_in, p_xz, DM_, DM_, XZW, 0, nullptr);
    transpose_bf16<<<dim3(DI_ / 32, XDP / 32), tb>>>(x_proj_w, p_w_xp, DI_, 96, XDP);     // 4
    transpose_bf16<<<dim3(RR_ / 32, DI_ / 32), tb>>>(dt_proj_w, p_w_dt, RR_, DI_, DI_);   // 5
    conv_silu_kernel<<<(ML_ * DI_) / 256, 256>>>(conv_w, conv_b);                         // 6
    // 7..10: xdbl partials = u @ x_proj_w  split-K=4 (K chunks of 512)
    for (int s = 0; s < KSPLIT; s++) {
        hmma_gemm<<<dim3(1, ML_ / 128), 256, SMEM_TOTAL>>>(
            p_ub + (size_t)s * (DI_ / KSPLIT), p_w_xp + (size_t)s * (DI_ / KSPLIT),
            p_xpp + (size_t)s * ML_ * XDP, DI_, DI_ / KSPLIT, XDP, 0, nullptr);
    }
    xp_reduce_kernel<<<(ML_ * XDP) / 256, 256>>>();                                       // 11
    // 12: dt = softplus(dt_r @ dt_proj_w + b)  [4096 x 2048], K=64
    hmma_gemm<<<dim3(DI_ / 128, ML_ / 128), 256, SMEM_TOTAL>>>(
        p_dtrb, p_w_dt, p_dt, RR_, RR_, DI_, 1, dt_proj_b);
    scan_kernel<<<2 * B2 * (DI_ / 16), 128>>>(A_log);                                     // 13
    gate_kernel<<<(ML_ * DI_) / 256, 256>>>(Dw);                                          // 14
    // 15: out = yg @ out_proj_w + x  [4096 x 1024], K=2048
    hmma_gemm<<<dim3(DM_ / 128, ML_ / 128), 256, SMEM_TOTAL>>>(
        p_ygb, p_w_out, out, DI_, DI_, DM_, 2, x);
}

// round 6
// speedup vs baseline: 1.4702x; 1.4702x over previous
#include <cuda_runtime.h>
#include <cuda_bf16.h>
#include <math.h>
#include <stdint.h>

// ---------------- dims ----------------
#define B2   2
#define L_   2048
#define DM_  1024
#define DI_  2048
#define NS_  16
#define RR_  64
#define ML_  (B2 * L_)          // 4096
#define XZW  (2 * DI_)          // 4096
#define XDP  128                // padded xdbl width (96 -> 128)
#define KSPLIT 4

// ---------------- scratch (device globals) ----------------
__device__ float g_xz  [(size_t)ML_ * XZW];
__device__ float g_u   [(size_t)ML_ * DI_];
__device__ float g_xdbl[(size_t)ML_ * XDP];
__device__ float g_xpp [KSPLIT][(size_t)ML_ * XDP];
__device__ float g_dt  [(size_t)ML_ * DI_];
__device__ float g_y   [(size_t)ML_ * DI_];
__device__ __nv_bfloat16 g_hb   [(size_t)ML_ * DM_];
__device__ __nv_bfloat16 g_ub   [(size_t)ML_ * DI_];
__device__ __nv_bfloat16 g_ygb  [(size_t)ML_ * DI_];
__device__ __nv_bfloat16 g_dtrb [(size_t)ML_ * RR_];
__device__ __nv_bfloat16 g_w_in [(size_t)XZW * DM_];
__device__ __nv_bfloat16 g_w_xp [(size_t)XDP * DI_];
__device__ __nv_bfloat16 g_w_dt [(size_t)DI_ * RR_];
__device__ __nv_bfloat16 g_w_out[(size_t)DM_ * DI_];

// ---------------- asm helpers ----------------
__device__ __forceinline__ uint32_t smem_u32(const void* p) {
    uint32_t a;
    asm("{ .reg .u64 t; cvta.to.shared.u64 t, %1; cvt.u32.u64 %0, t; }" : "=r"(a) : "l"(p));
    return a;
}
#define LDSM4(R0, R1, R2, R3, ADDR) \
    asm volatile("ldmatrix.sync.aligned.m8n8.x4.shared.b16 {%0,%1,%2,%3}, [%4];" \
        : "=r"(R0), "=r"(R1), "=r"(R2), "=r"(R3) : "r"(ADDR))
#define MMA16816(D, A0, A1, A2, A3, B0, B1) \
    asm volatile("mma.sync.aligned.m16n8k16.row.col.f32.bf16.bf16.f32 " \
        "{%0,%1,%2,%3}, {%4,%5,%6,%7}, {%8,%9}, {%0,%1,%2,%3};" \
        : "+f"((D)[0]), "+f"((D)[1]), "+f"((D)[2]), "+f"((D)[3]) \
        : "r"(A0), "r"(A1), "r"(A2), "r"(A3), "r"(B0), "r"(B1))
#define CP16(S, G) \
    asm volatile("cp.async.cg.shared.global [%0], [%1], 16;" :: "r"(S), "l"(G))
#define CPCOMMIT() asm volatile("cp.async.commit_group;")

#define NSTG 3
#define STAGE_BYTES 20480
#define ROW_B 80
#define SMEM_TOTAL (NSTG * STAGE_BYTES)   // 61440

// ---------------- bf16 HMMA GEMM: C[M,N] = A[M,Klen] @ Bt[N,Klen]^T ----------------
// Split-K via blockIdx.z: chunk z covers K range [z*Klen, (z+1)*Klen), output
// goes to C + z*Mtotal*ldc (caller passes per-z partial buffers contiguously).
// mode 0: C = acc ; 1: C = softplus(acc + e1[col]) ; 2: C = acc + e1[row*ldc + col]
__global__ void __launch_bounds__(256, 2) hmma_gemm(
    const __nv_bfloat16* __restrict__ A, const __nv_bfloat16* __restrict__ Bt,
    float* __restrict__ C, int lda, int Klen, int ldc, int mode,
    const float* __restrict__ e1, size_t zCstride)
{
    extern __shared__ __align__(128) char smem[];
    uint32_t sb = smem_u32(smem);
    int tid = threadIdx.x, wid = tid >> 5, lane = tid & 31;
    int row0 = blockIdx.y * 128, col0 = blockIdx.x * 128;
    int m0 = (wid & 3) * 32, n0 = (wid >> 2) * 64;
    size_t kbase = (size_t)blockIdx.z * Klen;
    C += (size_t)blockIdx.z * zCstride;

    int rA0 = tid >> 2, q0 = tid & 3;
    int rA1 = (tid + 256) >> 2;
    const char* gA0 = (const char*)(A  + (size_t)(row0 + rA0) * lda + kbase + q0 * 8);
    const char* gA1 = (const char*)(A  + (size_t)(row0 + rA1) * lda + kbase + q0 * 8);
    const char* gB0 = (const char*)(Bt + (size_t)(col0 + rA0) * lda + kbase + q0 * 8);
    const char* gB1 = (const char*)(Bt + (size_t)(col0 + rA1) * lda + kbase + q0 * 8);
    uint32_t sA0 = sb + rA0 * ROW_B + q0 * 16;
    uint32_t sA1 = sb + rA1 * ROW_B + q0 * 16;
    uint32_t sB0 = sA0 + 10240;
    uint32_t sB1 = sA1 + 10240;

    uint32_t aBase = sb + (m0 + (lane & 15)) * ROW_B + ((lane >> 4) << 4);
    uint32_t bBase = sb + 10240 + (n0 + (lane & 15)) * ROW_B + ((lane >> 4) << 4);

    float acc[2][8][4];
    #pragma unroll
    for (int i = 0; i < 2; i++)
        #pragma unroll
        for (int j = 0; j < 8; j++)
            #pragma unroll
            for (int v = 0; v < 4; v++) acc[i][j][v] = 0.f;

    const int NK = Klen >> 5;
    #pragma unroll
    for (int s = 0; s < NSTG - 1; s++) {
        if (s < NK) {
            uint32_t so = s * STAGE_BYTES;
            size_t go = (size_t)s * 64;
            CP16(sA0 + so, gA0 + go); CP16(sA1 + so, gA1 + go);
            CP16(sB0 + so, gB0 + go); CP16(sB1 + so, gB1 + go);
        }
        CPCOMMIT();
    }

    int so_c = 0;   // consume slot byte offset
    int so_p = (NSTG - 1) * STAGE_BYTES;  // produce slot
    for (int kt = 0; kt < NK; kt++) {
        asm volatile("cp.async.wait_group %0;" :: "n"(NSTG - 2));
        __syncthreads();
        if (kt + NSTG - 1 < NK) {
            size_t go = (size_t)(kt + NSTG - 1) * 64;
            CP16(sA0 + so_p, gA0 + go); CP16(sA1 + so_p, gA1 + go);
            CP16(sB0 + so_p, gB0 + go); CP16(sB1 + so_p, gB1 + go);
        }
        CPCOMMIT();

        uint32_t so = so_c;
        so_p = so_c;
        so_c = (so_c == (NSTG - 1) * STAGE_BYTES) ? 0 : so_c + STAGE_BYTES;

        #pragma unroll
        for (int s = 0; s < 2; s++) {
            uint32_t a[2][4], b[4][4];
            #pragma unroll
            for (int mt = 0; mt < 2; mt++)
                LDSM4(a[mt][0], a[mt][1], a[mt][2], a[mt][3],
                      aBase + so + s * 32 + mt * (16 * ROW_B));
            #pragma unroll
            for (int g = 0; g < 4; g++)
                LDSM4(b[g][0], b[g][1], b[g][2], b[g][3],
                      bBase + so + s * 32 + g * (16 * ROW_B));
            #pragma unroll
            for (int mt = 0; mt < 2; mt++)
                #pragma unroll
                for (int j = 0; j < 8; j++) {
                    int g = j >> 1, o = j & 1;
                    MMA16816(acc[mt][j], a[mt][0], a[mt][1], a[mt][2], a[mt][3],
                             b[g][o], b[g][o + 2]);
                }
        }
    }

    #pragma unroll
    for (int mt = 0; mt < 2; mt++) {
        #pragma unroll
        for (int j = 0; j < 8; j++) {
            int r_ = row0 + m0 + mt * 16 + (lane >> 2);
            int c_ = col0 + n0 + j * 8 + (lane & 3) * 2;
            #pragma unroll
            for (int h = 0; h < 2; h++) {
                float v0 = acc[mt][j][h * 2], v1 = acc[mt][j][h * 2 + 1];
                int rr = r_ + h * 8;
                if (mode == 1) {
                    v0 += e1[c_];
                    v1 += e1[c_ + 1];
                    v0 = fmaxf(v0, 0.f) + __logf(1.f + __expf(-fabsf(v0)));
                    v1 = fmaxf(v1, 0.f) + __logf(1.f + __expf(-fabsf(v1)));
                } else if (mode == 2) {
                    const float2 xv = *(const float2*)(e1 + (size_t)rr * ldc + c_);
                    v0 += xv.x; v1 += xv.y;
                }
                *(float2*)(C + (size_t)rr * ldc + c_) = make_float2(v0, v1);
            }
        }
    }
}

// ---------------- transpose fp32 [K,Nin] -> bf16 [Nout,K] (zero-pad) ----------------
__global__ void transpose_bf16(const float* __restrict__ in, __nv_bfloat16* __restrict__ out,
                               int K, int Nin, int Nout) {
    __shared__ float tile[32][33];
    int kb = blockIdx.x * 32, nb = blockIdx.y * 32;
    int tx = threadIdx.x, ty = threadIdx.y;
    #pragma unroll
    for (int i = 0; i < 32; i += 8) {
        int k = kb + ty + i, n = nb + tx;
        tile[ty + i][tx] = (n < Nin) ? in[(size_t)k * Nin + n] : 0.f;
    }
    __syncthreads();
    #pragma unroll
    for (int i = 0; i < 32; i += 8) {
        int n = nb + ty + i, k = kb + tx;
        out[(size_t)n * K + k] = __float2bfloat16(tile[tx][ty + i]);
    }
}

// ---------------- RMSNorm -> bf16 ----------------
__global__ void __launch_bounds__(256) rmsnorm_kernel(const float* __restrict__ x,
                                                      const float* __restrict__ w) {
    int row = blockIdx.x;
    int tid = threadIdx.x;
    float4 v = ((const float4*)(x + (size_t)row * DM_))[tid];
    float ss = v.x * v.x + v.y * v.y + v.z * v.z + v.w * v.w;
    #pragma unroll
    for (int o = 16; o > 0; o >>= 1) ss += __shfl_xor_sync(0xffffffffu, ss, o);
    __shared__ float sm[8];
    if ((tid & 31) == 0) sm[tid >> 5] = ss;
    __syncthreads();
    float tot = sm[0] + sm[1] + sm[2] + sm[3] + sm[4] + sm[5] + sm[6] + sm[7];
    float s = rsqrtf(tot * (1.0f / DM_) + 1e-5f);
    float4 wv = ((const float4*)w)[tid];
    __nv_bfloat162* op = (__nv_bfloat162*)(g_hb + (size_t)row * DM_);
    op[tid * 2]     = __floats2bfloat162_rn(v.x * s * wv.x, v.y * s * wv.y);
    op[tid * 2 + 1] = __floats2bfloat162_rn(v.z * s * wv.z, v.w * s * wv.w);
}

// ---------------- causal depthwise conv (K=4) + bias + SiLU ----------------
__global__ void __launch_bounds__(256) conv_silu_kernel(const float* __restrict__ conv_w,
                                                        const float* __restrict__ conv_b) {
    int idx = blockIdx.x * 256 + threadIdx.x;
    int d = idx & (DI_ - 1);
    int row = idx >> 11;
    int t = row & (L_ - 1);
    float w0 = conv_w[d * 4 + 0], w1 = conv_w[d * 4 + 1];
    float w2 = conv_w[d * 4 + 2], w3 = conv_w[d * 4 + 3];
    const float* base = g_xz + (size_t)row * XZW + d;
    float acc = conv_b[d] + base[0] * w3;
    if (t >= 1) acc = fmaf(base[-(ptrdiff_t)XZW], w2, acc);
    if (t >= 2) acc = fmaf(base[-2 * (ptrdiff_t)XZW], w1, acc);
    if (t >= 3) acc = fmaf(base[-3 * (ptrdiff_t)XZW], w0, acc);
    float u = acc / (1.f + __expf(-acc));
    g_u[idx] = u;
    g_ub[idx] = __float2bfloat16(u);
}

// ---------------- reduce split-K partials -> g_xdbl fp32 + g_dtrb bf16 ----------------
__global__ void __launch_bounds__(256) xp_reduce_kernel() {
    int idx = blockIdx.x * 256 + threadIdx.x;
    float s = g_xpp[0][idx] + g_xpp[1][idx] + g_xpp[2][idx] + g_xpp[3][idx];
    g_xdbl[idx] = s;
    int j = idx & (XDP - 1);
    if (j < RR_) g_dtrb[((size_t)(idx >> 7) << 6) + j] = __float2bfloat16(s);
}

// ---------------- selective scan (R3-proven shape: 256 blocks x 256 thr) ----------------
__global__ void __launch_bounds__(256) scan_kernel(const float* __restrict__ A_log) {
    int tid = threadIdx.x;
    int lane = tid & 31;
    int n = lane & 15;
    int ch = tid >> 4;
    int b = blockIdx.x >> 7;
    int d = ((blockIdx.x & 127) << 4) + ch;
    float A_n = -expf(A_log[d * NS_ + n]);
    float hst = 0.f;
    const float* dtp = g_dt + (size_t)b * L_ * DI_ + d;
    const float* up  = g_u  + (size_t)b * L_ * DI_ + d;
    const float* xb  = g_xdbl + (size_t)b * L_ * XDP;
    float* yp = g_y + (size_t)b * L_ * DI_ + d;
    #pragma unroll 2
    for (int t = 0; t < L_; t++) {
        float dt_v = __ldg(dtp + (size_t)t * DI_);
        float u_v  = __ldg(up  + (size_t)t * DI_);
        float Bn = __ldg(xb + t * XDP + RR_ + n);
        float Cn = __ldg(xb + t * XDP + RR_ + NS_ + n);
        float dA = __expf(dt_v * A_n);
        hst = fmaf(dA, hst, dt_v * u_v * Bn);
        float p = hst * Cn;
        p += __shfl_xor_sync(0xffffffffu, p, 8);
        p += __shfl_xor_sync(0xffffffffu, p, 4);
        p += __shfl_xor_sync(0xffffffffu, p, 2);
        p += __shfl_xor_sync(0xffffffffu, p, 1);
        if (n == 0) yp[(size_t)t * DI_] = p;
    }
}

// ---------------- gating ----------------
__global__ void __launch_bounds__(256) gate_kernel(const float* __restrict__ Dw) {
    int idx = blockIdx.x * 256 + threadIdx.x;
    int d = idx & (DI_ - 1);
    int row = idx >> 11;
    float z = g_xz[(size_t)row * XZW + DI_ + d];
    float sz = z / (1.f + __expf(-z));
    g_ygb[idx] = __float2bfloat16((g_y[idx] + g_u[idx] * Dw[d]) * sz);
}

// ---------------- launch ----------------
extern "C" void kernel_launch(void* const* d_in, const int* in_sizes, int n_in,
                              void* d_out, int out_size) {
    (void)in_sizes; (void)n_in; (void)out_size;
    const float* x          = (const float*)d_in[0];
    const float* norm_w     = (const float*)d_in[2];
    const float* in_proj_w  = (const float*)d_in[3];
    const float* conv_w     = (const float*)d_in[4];
    const float* conv_b     = (const float*)d_in[5];
    const float* x_proj_w   = (const float*)d_in[6];
    const float* dt_proj_w  = (const float*)d_in[7];
    const float* dt_proj_b  = (const float*)d_in[8];
    const float* A_log      = (const float*)d_in[9];
    const float* Dw         = (const float*)d_in[10];
    const float* out_proj_w = (const float*)d_in[11];
    float* out = (float*)d_out;

    float *p_xz, *p_dt, *p_xpp;
    __nv_bfloat16 *p_hb, *p_ub, *p_ygb, *p_dtrb, *p_w_in, *p_w_xp, *p_w_dt, *p_w_out;
    cudaGetSymbolAddress((void**)&p_xz, g_xz);
    cudaGetSymbolAddress((void**)&p_dt, g_dt);
    cudaGetSymbolAddress((void**)&p_xpp, g_xpp);
    cudaGetSymbolAddress((void**)&p_hb, g_hb);
    cudaGetSymbolAddress((void**)&p_ub, g_ub);
    cudaGetSymbolAddress((void**)&p_ygb, g_ygb);
    cudaGetSymbolAddress((void**)&p_dtrb, g_dtrb);
    cudaGetSymbolAddress((void**)&p_w_in, g_w_in);
    cudaGetSymbolAddress((void**)&p_w_xp, g_w_xp);
    cudaGetSymbolAddress((void**)&p_w_dt, g_w_dt);
    cudaGetSymbolAddress((void**)&p_w_out, g_w_out);

    cudaFuncSetAttribute(hmma_gemm, cudaFuncAttributeMaxDynamicSharedMemorySize, SMEM_TOTAL);
    cudaFuncSetAttribute(hmma_gemm, cudaFuncAttributePreferredSharedMemoryCarveout, 100);

    dim3 tb(32, 8);
    transpose_bf16<<<dim3(DM_ / 32, XZW / 32), tb>>>(in_proj_w, p_w_in, DM_, XZW, XZW);   // 0
    rmsnorm_kernel<<<ML_, 256>>>(x, norm_w);                                              // 1
    transpose_bf16<<<dim3(DI_ / 32, DM_ / 32), tb>>>(out_proj_w, p_w_out, DI_, DM_, DM_); // 2
    // 3: xz = h @ in_proj_w   [4096 x 4096], K=1024   (profiled launch)
    hmma_gemm<<<dim3(XZW / 128, ML_ / 128), 256, SMEM_TOTAL>>>(
        p_hb, p_w_in, p_xz, DM_, DM_, XZW, 0, nullptr, 0);
    transpose_bf16<<<dim3(DI_ / 32, XDP / 32), tb>>>(x_proj_w, p_w_xp, DI_, 96, XDP);     // 4
    transpose_bf16<<<dim3(RR_ / 32, DI_ / 32), tb>>>(dt_proj_w, p_w_dt, RR_, DI_, DI_);   // 5
    conv_silu_kernel<<<(ML_ * DI_) / 256, 256>>>(conv_w, conv_b);                         // 6
    // 7: xdbl partials = u @ x_proj_w  split-K=4 in ONE launch (grid.z)
    hmma_gemm<<<dim3(1, ML_ / 128, KSPLIT), 256, SMEM_TOTAL>>>(
        p_ub, p_w_xp, p_xpp, DI_, DI_ / KSPLIT, XDP, 0, nullptr, (size_t)ML_ * XDP);
    xp_reduce_kernel<<<(ML_ * XDP) / 256, 256>>>();                                       // 8
    // 9: dt = softplus(dt_r @ dt_proj_w + b)  [4096 x 2048], K=64
    hmma_gemm<<<dim3(DI_ / 128, ML_ / 128), 256, SMEM_TOTAL>>>(
        p_dtrb, p_w_dt, p_dt, RR_, RR_, DI_, 1, dt_proj_b, 0);
    scan_kernel<<<B2 * (DI_ / 16), 256>>>(A_log);                                         // 10
    gate_kernel<<<(ML_ * DI_) / 256, 256>>>(Dw);                                          // 11
    // 12: out = yg @ out_proj_w + x  [4096 x 1024], K=2048
    hmma_gemm<<<dim3(DM_ / 128, ML_ / 128), 256, SMEM_TOTAL>>>(
        p_ygb, p_w_out, out, DI_, DI_, DM_, 2, x, 0);
}